// round 14
// baseline (speedup 1.0000x reference)
#include <cuda_runtime.h>
#include <cuda_fp16.h>
#include <cstdint>

// ---------------- problem constants ----------------
#define NSEL   8
#define CIN    128
#define COUTC  128
#define HDIM   128
#define WDIM   128
#define HWP    16384            // HDIM*WDIM
#define NPIX   131072           // 8*HWP
#define NELEM  (NPIX * CIN)
#define KC     64               // K per ktile: one tap x 64 ci
#define NKT    18
#define NSUB   36               // reorg sub-tiles (one tap x 32 ci)
#define PX_TILE 128
#define NBLK   512              // NPIX/256
#define MAXTILES 1031
#define INVALID_PIX 0xFFFFFFFFu

#define AFRAG_B 16384           // 128 px x 128B
#define BFRAG_B 8192            // co-half: 2 sub x 8 jj x 32 lanes x 16B
#define STAGE_B (AFRAG_B + BFRAG_B)
#define NSTAGE  3
#define SMEM_BYTES (NSTAGE*STAGE_B + 512)

// ---------------- scratch (static device; no allocs) ----------------
__device__ unsigned int  g_count[NSEL];
__device__ unsigned int  g_tile[NSEL + 1];
__device__ unsigned int  g_list[NSEL][NPIX];                 // 4 MB
__device__ unsigned char g_bs[NPIX];
__device__ unsigned int  g_bhist[NBLK][NSEL];
__device__ unsigned int  g_bbase[NBLK][NSEL];
__device__ __align__(16) __half g_wbh[NSEL * NSUB * 4096];   // 2.25 MB frag-record fp16 B tiles
__device__ __align__(16) __half g_in_t[NELEM];               // 32 MB channel-last fp16 input

// ---------------- PTX helpers ----------------
static __device__ __forceinline__ uint32_t smem_u32(const void* p) {
    uint32_t a;
    asm("{ .reg .u64 t; cvta.to.shared.u64 t, %1; cvt.u32.u64 %0, t; }" : "=r"(a) : "l"(p));
    return a;
}
#define CP_ASYNC16(dst, src) \
    asm volatile("cp.async.cg.shared.global [%0], [%1], 16;" :: "r"(dst), "l"(src))
#define CP_ASYNC16Z(dst, src, sz) \
    asm volatile("cp.async.cg.shared.global [%0], [%1], 16, %2;" :: "r"(dst), "l"(src), "r"(sz))
#define CP_COMMIT() asm volatile("cp.async.commit_group;" ::: "memory")
#define CP_WAIT0()  asm volatile("cp.async.wait_group 0;" ::: "memory")
#define CP_WAIT1()  asm volatile("cp.async.wait_group 1;" ::: "memory")

#define LDS128(v, addr) \
    asm volatile("ld.shared.v4.b32 {%0,%1,%2,%3}, [%4];" \
        : "=r"((v)[0]), "=r"((v)[1]), "=r"((v)[2]), "=r"((v)[3]) : "r"(addr))

static __device__ __forceinline__ void mma_f16(float c[4], uint32_t a0, uint32_t a1,
                                               uint32_t a2, uint32_t a3,
                                               uint32_t b0, uint32_t b1) {
    asm volatile(
        "mma.sync.aligned.m16n8k16.row.col.f32.f16.f16.f32 "
        "{%0,%1,%2,%3}, {%4,%5,%6,%7}, {%8,%9}, {%0,%1,%2,%3};"
        : "+f"(c[0]), "+f"(c[1]), "+f"(c[2]), "+f"(c[3])
        : "r"(a0), "r"(a1), "r"(a2), "r"(a3), "r"(b0), "r"(b1));
}

// pair permutation within each 32-ci block: content pair c at pos = (c&3)*4 + (c>>2)

// ---------------------------------------------------------------------------
// Kernel 0: transpose input [b][ci][y][x] fp32 -> g_in_t[(b,y,x)][ci'] fp16
// ---------------------------------------------------------------------------
__global__ void tr_kernel(const float* __restrict__ in) {
    __shared__ __half tile[32][33];
    const int pb = blockIdx.x;
    const int cb = blockIdx.y;
    const int t  = threadIdx.x;

    const int ci_l = t >> 3;
    const int x4   = (t & 7) * 4;
    const int p0   = pb * 32;
    const int b    = p0 >> 14;
    const int hw   = (p0 & (HWP - 1)) + x4;
    float4 v = *(const float4*)(in + ((size_t)b * CIN + cb * 32 + ci_l) * HWP + hw);
    tile[ci_l][x4 + 0] = __float2half_rn(v.x);
    tile[ci_l][x4 + 1] = __float2half_rn(v.y);
    tile[ci_l][x4 + 2] = __float2half_rn(v.z);
    tile[ci_l][x4 + 3] = __float2half_rn(v.w);
    __syncthreads();

    if (t < 128) {
        const int px_l = t >> 2;
        const int u    = t & 3;
        __half h[8];
#pragma unroll
        for (int m = 0; m < 8; m++) {
            int oh  = u * 8 + m;
            int pos = oh >> 1, hi = oh & 1;
            int c   = (pos >> 2) + (pos & 3) * 4;
            h[m] = tile[c * 2 + hi][px_l];
        }
        *(uint4*)((char*)g_in_t + ((size_t)(p0 + px_l) << 8) + (cb << 6) + (u << 4)) =
            *(const uint4*)h;
    }
}

// ---------------------------------------------------------------------------
// Kernel 1: argmax gate + per-block histograms
// ---------------------------------------------------------------------------
__global__ void hist_kernel(const float* __restrict__ selector) {
    __shared__ unsigned int h[NSEL];
    int tid = threadIdx.x;
    if (tid < NSEL) h[tid] = 0u;
    __syncthreads();

    int p  = blockIdx.x * 256 + tid;
    int b  = p >> 14;
    int hw = p & (HWP - 1);
    const float* sp = selector + (size_t)b * NSEL * HWP + hw;
    float best = sp[0];
    int bs = 0;
#pragma unroll
    for (int s = 1; s < NSEL; s++) {
        float v = sp[(size_t)s * HWP];
        if (v > best) { best = v; bs = s; }
    }
    g_bs[p] = (unsigned char)bs;
    atomicAdd(&h[bs], 1u);
    __syncthreads();
    if (tid < NSEL) g_bhist[blockIdx.x][tid] = h[tid];
}

// ---------------------------------------------------------------------------
// Kernel 2: exclusive scan + tile prefix
// ---------------------------------------------------------------------------
__global__ void scan_kernel() {
    __shared__ unsigned int part[NSEL][32];
    int tid = threadIdx.x;
    int s = tid & 7, c = tid >> 3;
    unsigned int sum = 0;
#pragma unroll
    for (int b = c * 16; b < c * 16 + 16; b++) sum += g_bhist[b][s];
    part[s][c] = sum;
    __syncthreads();
    if (tid < NSEL) {
        unsigned int run = 0;
#pragma unroll
        for (int c2 = 0; c2 < 32; c2++) {
            unsigned int t = part[tid][c2];
            part[tid][c2] = run;
            run += t;
        }
        g_count[tid] = run;
    }
    __syncthreads();
    unsigned int run = part[s][c];
    for (int b = c * 16; b < c * 16 + 16; b++) {
        g_bbase[b][s] = run;
        run += g_bhist[b][s];
    }
    __syncthreads();
    if (tid == 0) {
        unsigned int tot = 0;
#pragma unroll
        for (int i = 0; i < NSEL; i++) {
            g_tile[i] = tot;
            tot += (g_count[i] + PX_TILE - 1) >> 7;
        }
        g_tile[NSEL] = tot;
    }
}

// ---------------------------------------------------------------------------
// Kernel 3: ordered scatter -> sorted per-bin pixel lists
// ---------------------------------------------------------------------------
__global__ void scatter_kernel() {
    __shared__ unsigned int wh[8][NSEL];
    int tid = threadIdx.x;
    int wid = tid >> 5;
    if (tid < 64) ((unsigned int*)wh)[tid] = 0u;
    __syncthreads();

    int p = blockIdx.x * 256 + tid;
    int bs = g_bs[p];
    unsigned int mask = __match_any_sync(0xFFFFFFFFu, bs);
    unsigned int lt   = (1u << (tid & 31)) - 1u;
    unsigned int rank = __popc(mask & lt);
    if (rank == 0) wh[wid][bs] = __popc(mask);
    __syncthreads();
    if (tid < NSEL) {
        unsigned int run = 0;
#pragma unroll
        for (int w = 0; w < 8; w++) {
            unsigned int t = wh[w][tid];
            wh[w][tid] = run;
            run += t;
        }
    }
    __syncthreads();
    unsigned int idx = g_bbase[blockIdx.x][bs] + wh[wid][bs] + rank;
    g_list[bs][idx] = (unsigned int)p;
}

// ---------------------------------------------------------------------------
// Kernel 4: weight repack -> fp16 frag-record B sub-tiles (8KB each), r-major.
// (unchanged from R12/R13)
// ---------------------------------------------------------------------------
__global__ void reorg_kernel(const float* __restrict__ w) {
    int t = blockIdx.x * 256 + threadIdx.x;       // NSEL*NSUB*4096 threads
    int e    = t & 4095;
    int tile = t >> 12;
    int kt = tile % NSUB;
    int s  = tile / NSUB;
    int m    = e & 7;
    int lane = (e >> 3) & 31;
    int jj   = e >> 8;
    int u4 = m >> 1, hi = m & 1;
    int kq = lane & 3;
    int kit = (kq + u4 * 4) * 2 + hi;
    int co  = jj * 8 + (lane >> 2);
    int ci  = ((kt & 3) << 5) + kit;
    int tap = kt >> 2;
    g_wbh[t] = __float2half_rn(w[(((size_t)co * CIN + ci) * NSEL + s) * 9 + tap]);
}

// ---------------------------------------------------------------------------
// Kernel 5: grouped implicit-GEMM conv, fp16 m16n8k16, N-split CTAs.
//   CTA = 128 px x 64 co (blockIdx.y = co half); 8 warps = 2(M) x 4(N),
//   warp tile 64px x 16co, acc 32 regs -> 3 CTAs/SM (24 warps).
//   A path identical to R13 (contiguous gather, parity-swizzled records).
// ---------------------------------------------------------------------------
__global__ void __launch_bounds__(256, 3)
conv_kernel(const float* __restrict__ bias, float* __restrict__ out) {
    const unsigned int bid = blockIdx.x;
    if (bid >= g_tile[NSEL]) return;
    const int coH = blockIdx.y;                   // 0/1: co 0-63 / 64-127
    int s = 0;
#pragma unroll
    for (int i = 1; i < NSEL; i++) s += (bid >= g_tile[i]) ? 1 : 0;
    const unsigned int cnt = g_count[s];
    const int tile0 = (int)(bid - g_tile[s]) * PX_TILE;

    extern __shared__ char dsm[];
    const uint32_t Abase = smem_u32(dsm);         // stage layout: [A 16KB | B 8KB] x 3
    unsigned int* spix = (unsigned int*)(dsm + NSTAGE * STAGE_B);

    const int tid  = threadIdx.x;
    const int wid  = tid >> 5;
    const int lane = tid & 31;

    if (tid < PX_TILE) {
        int idx = tile0 + tid;
        spix[tid] = (idx < (int)cnt) ? g_list[s][idx] : INVALID_PIX;
    }
    __syncthreads();

    // ---- gather assignment: px = tid>>1, 64B sub-block kg = tid&1 ----
    const int gpx = tid >> 1;
    const int kg  = tid & 1;
    const unsigned int gp = spix[gpx];
    const bool gvalid = (gp != INVALID_PIX);
    const int gh = (gp >> 7) & 127, gw = gp & 127;
    const size_t pxbase = (size_t)(gp >> 14) << 14;
    const uint32_t asub = (uint32_t)((kg ^ (gpx & 1)) * 64);

    // ---- compute assignment: 8 warps = 2(M) x 4(N over 64 co) ----
    const int wm = wid & 1;
    const int wn = wid >> 1;                      // 0..3, 16 co each
    const int rr = lane >> 2;
    const uint32_t kq16 = (uint32_t)(lane & 3) * 16u;

    float acc[4][2][4];
#pragma unroll
    for (int i = 0; i < 4; i++)
#pragma unroll
        for (int j = 0; j < 2; j++)
#pragma unroll
            for (int e = 0; e < 4; e++) acc[i][j][e] = 0.f;

    const char* wtiles = (const char*)g_wbh + (size_t)s * NSUB * 8192;

    // ---- A fill: identical to R13 ----
    auto fillA = [&](int kt, int buf) {
        const int tap = kt >> 1;
        const int kh = (tap * 11) >> 5;
        const int kw = tap - kh * 3;
        const int y = gh + kh - 1, x = gw + kw - 1;
        const unsigned int sz =
            (gvalid && (unsigned)y < 128u && (unsigned)x < 128u) ? 16u : 0u;
        const char* src = sz
            ? (const char*)g_in_t + ((pxbase + (size_t)(y * 128 + x)) << 8)
                  + ((kt & 1) << 7) + (kg << 6)
            : (const char*)g_in_t;
        const uint32_t dst = Abase + buf * STAGE_B + (uint32_t)gpx * 128u + asub;
        CP_ASYNC16Z(dst,       src,      sz);
        CP_ASYNC16Z(dst + 16u, src + 16, sz);
        CP_ASYNC16Z(dst + 32u, src + 32, sz);
        CP_ASYNC16Z(dst + 48u, src + 48, sz);
    };

    // ---- B fill: this CTA's 4KB jj-half of sub-tiles {2kt, 2kt+1} ----
    auto fillB = [&](int kt, int buf) {
        const int half128 = tid >> 7;             // which sub-tile
        const int r128    = tid & 127;
        const char* src = wtiles + (size_t)(2 * kt + half128) * 8192 +
                          coH * 4096 + r128 * 32;
        const uint32_t dst = Abase + buf * STAGE_B + AFRAG_B +
                             (uint32_t)(half128 * 4096 + r128 * 32);
        CP_ASYNC16(dst,       src);
        CP_ASYNC16(dst + 16u, src + 16);
    };

    auto compute = [&](int buf) {
        const uint32_t Ab = Abase + buf * STAGE_B;
        const uint32_t Bb = Ab + AFRAG_B;
#pragma unroll
        for (int sub = 0; sub < 2; sub++) {
            uint32_t alo[4][4], ahi[4][4];
#pragma unroll
            for (int i = 0; i < 4; i++) {
                const int row = wm * 64 + i * 16 + rr;
                const uint32_t rowa = Ab + (uint32_t)(row * 128) + kq16 +
                                      (uint32_t)(((sub ^ (rr & 1)) * 64));
                LDS128(alo[i], rowa);
                LDS128(ahi[i], rowa + 1024u);
            }
#pragma unroll
            for (int j = 0; j < 2; j++) {
                uint32_t bf[4];
                LDS128(bf, Bb + (uint32_t)(sub * 4096) +
                           (uint32_t)((wn * 2 + j) * 512) + (uint32_t)lane * 16u);
#pragma unroll
                for (int i = 0; i < 4; i++) {
                    mma_f16(acc[i][j], alo[i][0], ahi[i][0], alo[i][1], ahi[i][1],
                            bf[0], bf[1]);
                    mma_f16(acc[i][j], alo[i][2], ahi[i][2], alo[i][3], ahi[i][3],
                            bf[2], bf[3]);
                }
            }
        }
    };

    // ---------- prologue: stages 0, 1 ----------
    fillB(0, 0); fillA(0, 0); CP_COMMIT();
    fillB(1, 1); fillA(1, 1); CP_COMMIT();
    CP_WAIT1();
    __syncthreads();

    // ---------- main loop ----------
#pragma unroll 1
    for (int kt = 0; kt < NKT; kt++) {
        const int buf = kt % 3;
        const int nb  = (kt + 2) % 3;
        const bool more2 = (kt + 2 < NKT);
        if (more2) { fillB(kt + 2, nb); fillA(kt + 2, nb); CP_COMMIT(); }
        compute(buf);
        if (kt + 1 < NKT) {
            if (more2) { CP_WAIT1(); } else { CP_WAIT0(); }
            __syncthreads();
        }
    }

    // ---------- epilogue: bias + scattered stores ----------
    const int kq = lane & 3;
    float bv[2][2];
#pragma unroll
    for (int j = 0; j < 2; j++) {
        int co = coH * 64 + wn * 16 + j * 8 + 2 * kq;
        bv[j][0] = __ldg(&bias[co]);
        bv[j][1] = __ldg(&bias[co + 1]);
    }
#pragma unroll
    for (int i = 0; i < 4; i++) {
        const int r0 = wm * 64 + i * 16 + rr;
#pragma unroll
        for (int half = 0; half < 2; half++) {
            const unsigned int p = spix[r0 + half * 8];
            if (p == INVALID_PIX) continue;
            const int pb = p >> 14;
            const int hw = p & (HWP - 1);
            float* ob = out + ((size_t)pb * COUTC) * HWP + hw;
#pragma unroll
            for (int j = 0; j < 2; j++) {
                const int co = coH * 64 + wn * 16 + j * 8 + 2 * kq;
                ob[(size_t)co * HWP]       = acc[i][j][half * 2]     + bv[j][0];
                ob[(size_t)(co + 1) * HWP] = acc[i][j][half * 2 + 1] + bv[j][1];
            }
        }
    }
}

// ---------------------------------------------------------------------------
extern "C" void kernel_launch(void* const* d_in, const int* in_sizes, int n_in,
                              void* d_out, int out_size) {
    const float* input    = (const float*)d_in[0];   // [8,128,128,128]
    const float* selector = (const float*)d_in[1];   // [8,8,128,128]
    const float* weight   = (const float*)d_in[2];   // [128,128,8,3,3]
    const float* bias     = (const float*)d_in[3];   // [128]
    float* out = (float*)d_out;                      // [8,128,128,128]

    static bool attr_done = false;
    if (!attr_done) {
        cudaFuncSetAttribute(conv_kernel, cudaFuncAttributeMaxDynamicSharedMemorySize, SMEM_BYTES);
        attr_done = true;
    }

    tr_kernel<<<dim3(NPIX / 32, CIN / 32), 256>>>(input);
    hist_kernel<<<NBLK, 256>>>(selector);
    scan_kernel<<<1, 256>>>();
    scatter_kernel<<<NBLK, 256>>>();
    reorg_kernel<<<(NSEL * NSUB * 4096) / 256, 256>>>(weight);
    conv_kernel<<<dim3(MAXTILES, 2), 256, SMEM_BYTES>>>(bias, out);
}

// round 15
// speedup vs baseline: 1.0457x; 1.0457x over previous
#include <cuda_runtime.h>
#include <cuda_fp16.h>
#include <cstdint>

// ---------------- problem constants ----------------
#define NSEL   8
#define CIN    128
#define COUTC  128
#define HDIM   128
#define WDIM   128
#define HWP    16384            // HDIM*WDIM
#define NPIX   131072           // 8*HWP
#define NELEM  (NPIX * CIN)
#define KC     64               // K per ktile: one tap x 64 ci
#define NKT    18
#define NSUB   36               // reorg sub-tiles (one tap x 32 ci)
#define PX_TILE 64
#define NBLK   512              // NPIX/256
#define MAXTILES 2056           // 2048 + 8 (per-bin ceil rounding)
#define INVALID_PIX 0xFFFFFFFFu

#define AFRAG_B 8192            // 64 px x 128B
#define BFRAG_B 16384           // 2 sub x 16 jj x 32 lanes x 16B
#define STAGE_B (AFRAG_B + BFRAG_B)
#define NSTAGE  3
#define SMEM_BYTES (NSTAGE*STAGE_B + 512)   // 74240

// ---------------- scratch (static device; no allocs) ----------------
__device__ unsigned int  g_count[NSEL];
__device__ unsigned int  g_tile[NSEL + 1];
__device__ unsigned int  g_list[NSEL][NPIX];                 // 4 MB
__device__ unsigned char g_bs[NPIX];
__device__ unsigned int  g_bhist[NBLK][NSEL];
__device__ unsigned int  g_bbase[NBLK][NSEL];
__device__ __align__(16) __half g_wbh[NSEL * NSUB * 4096];   // 2.25 MB frag-record fp16 B tiles
__device__ __align__(16) __half g_in_t[NELEM];               // 32 MB channel-last fp16 input

// ---------------- PTX helpers ----------------
static __device__ __forceinline__ uint32_t smem_u32(const void* p) {
    uint32_t a;
    asm("{ .reg .u64 t; cvta.to.shared.u64 t, %1; cvt.u32.u64 %0, t; }" : "=r"(a) : "l"(p));
    return a;
}
#define CP_ASYNC16(dst, src) \
    asm volatile("cp.async.cg.shared.global [%0], [%1], 16;" :: "r"(dst), "l"(src))
#define CP_ASYNC16Z(dst, src, sz) \
    asm volatile("cp.async.cg.shared.global [%0], [%1], 16, %2;" :: "r"(dst), "l"(src), "r"(sz))
#define CP_COMMIT() asm volatile("cp.async.commit_group;" ::: "memory")
#define CP_WAIT0()  asm volatile("cp.async.wait_group 0;" ::: "memory")
#define CP_WAIT1()  asm volatile("cp.async.wait_group 1;" ::: "memory")

#define LDS128(v, addr) \
    asm volatile("ld.shared.v4.b32 {%0,%1,%2,%3}, [%4];" \
        : "=r"((v)[0]), "=r"((v)[1]), "=r"((v)[2]), "=r"((v)[3]) : "r"(addr))

static __device__ __forceinline__ void mma_f16(float c[4], uint32_t a0, uint32_t a1,
                                               uint32_t a2, uint32_t a3,
                                               uint32_t b0, uint32_t b1) {
    asm volatile(
        "mma.sync.aligned.m16n8k16.row.col.f32.f16.f16.f32 "
        "{%0,%1,%2,%3}, {%4,%5,%6,%7}, {%8,%9}, {%0,%1,%2,%3};"
        : "+f"(c[0]), "+f"(c[1]), "+f"(c[2]), "+f"(c[3])
        : "r"(a0), "r"(a1), "r"(a2), "r"(a3), "r"(b0), "r"(b1));
}

// pair permutation within each 32-ci block: content pair c at pos = (c&3)*4 + (c>>2)

// ---------------------------------------------------------------------------
// Kernel 0: transpose input [b][ci][y][x] fp32 -> g_in_t[(b,y,x)][ci'] fp16
// ---------------------------------------------------------------------------
__global__ void tr_kernel(const float* __restrict__ in) {
    __shared__ __half tile[32][33];
    const int pb = blockIdx.x;
    const int cb = blockIdx.y;
    const int t  = threadIdx.x;

    const int ci_l = t >> 3;
    const int x4   = (t & 7) * 4;
    const int p0   = pb * 32;
    const int b    = p0 >> 14;
    const int hw   = (p0 & (HWP - 1)) + x4;
    float4 v = *(const float4*)(in + ((size_t)b * CIN + cb * 32 + ci_l) * HWP + hw);
    tile[ci_l][x4 + 0] = __float2half_rn(v.x);
    tile[ci_l][x4 + 1] = __float2half_rn(v.y);
    tile[ci_l][x4 + 2] = __float2half_rn(v.z);
    tile[ci_l][x4 + 3] = __float2half_rn(v.w);
    __syncthreads();

    if (t < 128) {
        const int px_l = t >> 2;
        const int u    = t & 3;
        __half h[8];
#pragma unroll
        for (int m = 0; m < 8; m++) {
            int oh  = u * 8 + m;
            int pos = oh >> 1, hi = oh & 1;
            int c   = (pos >> 2) + (pos & 3) * 4;
            h[m] = tile[c * 2 + hi][px_l];
        }
        *(uint4*)((char*)g_in_t + ((size_t)(p0 + px_l) << 8) + (cb << 6) + (u << 4)) =
            *(const uint4*)h;
    }
}

// ---------------------------------------------------------------------------
// Kernel 1: argmax gate + per-block histograms
// ---------------------------------------------------------------------------
__global__ void hist_kernel(const float* __restrict__ selector) {
    __shared__ unsigned int h[NSEL];
    int tid = threadIdx.x;
    if (tid < NSEL) h[tid] = 0u;
    __syncthreads();

    int p  = blockIdx.x * 256 + tid;
    int b  = p >> 14;
    int hw = p & (HWP - 1);
    const float* sp = selector + (size_t)b * NSEL * HWP + hw;
    float best = sp[0];
    int bs = 0;
#pragma unroll
    for (int s = 1; s < NSEL; s++) {
        float v = sp[(size_t)s * HWP];
        if (v > best) { best = v; bs = s; }
    }
    g_bs[p] = (unsigned char)bs;
    atomicAdd(&h[bs], 1u);
    __syncthreads();
    if (tid < NSEL) g_bhist[blockIdx.x][tid] = h[tid];
}

// ---------------------------------------------------------------------------
// Kernel 2: exclusive scan + tile prefix (64-px tiles)
// ---------------------------------------------------------------------------
__global__ void scan_kernel() {
    __shared__ unsigned int part[NSEL][32];
    int tid = threadIdx.x;
    int s = tid & 7, c = tid >> 3;
    unsigned int sum = 0;
#pragma unroll
    for (int b = c * 16; b < c * 16 + 16; b++) sum += g_bhist[b][s];
    part[s][c] = sum;
    __syncthreads();
    if (tid < NSEL) {
        unsigned int run = 0;
#pragma unroll
        for (int c2 = 0; c2 < 32; c2++) {
            unsigned int t = part[tid][c2];
            part[tid][c2] = run;
            run += t;
        }
        g_count[tid] = run;
    }
    __syncthreads();
    unsigned int run = part[s][c];
    for (int b = c * 16; b < c * 16 + 16; b++) {
        g_bbase[b][s] = run;
        run += g_bhist[b][s];
    }
    __syncthreads();
    if (tid == 0) {
        unsigned int tot = 0;
#pragma unroll
        for (int i = 0; i < NSEL; i++) {
            g_tile[i] = tot;
            tot += (g_count[i] + PX_TILE - 1) >> 6;
        }
        g_tile[NSEL] = tot;
    }
}

// ---------------------------------------------------------------------------
// Kernel 3: ordered scatter -> sorted per-bin pixel lists
// ---------------------------------------------------------------------------
__global__ void scatter_kernel() {
    __shared__ unsigned int wh[8][NSEL];
    int tid = threadIdx.x;
    int wid = tid >> 5;
    if (tid < 64) ((unsigned int*)wh)[tid] = 0u;
    __syncthreads();

    int p = blockIdx.x * 256 + tid;
    int bs = g_bs[p];
    unsigned int mask = __match_any_sync(0xFFFFFFFFu, bs);
    unsigned int lt   = (1u << (tid & 31)) - 1u;
    unsigned int rank = __popc(mask & lt);
    if (rank == 0) wh[wid][bs] = __popc(mask);
    __syncthreads();
    if (tid < NSEL) {
        unsigned int run = 0;
#pragma unroll
        for (int w = 0; w < 8; w++) {
            unsigned int t = wh[w][tid];
            wh[w][tid] = run;
            run += t;
        }
    }
    __syncthreads();
    unsigned int idx = g_bbase[blockIdx.x][bs] + wh[wid][bs] + rank;
    g_list[bs][idx] = (unsigned int)p;
}

// ---------------------------------------------------------------------------
// Kernel 4: weight repack -> fp16 frag-record B sub-tiles (8KB each), r-major.
// (unchanged from R12/R13)
// ---------------------------------------------------------------------------
__global__ void reorg_kernel(const float* __restrict__ w) {
    int t = blockIdx.x * 256 + threadIdx.x;       // NSEL*NSUB*4096 threads
    int e    = t & 4095;
    int tile = t >> 12;
    int kt = tile % NSUB;
    int s  = tile / NSUB;
    int m    = e & 7;
    int lane = (e >> 3) & 31;
    int jj   = e >> 8;
    int u4 = m >> 1, hi = m & 1;
    int kq = lane & 3;
    int kit = (kq + u4 * 4) * 2 + hi;
    int co  = jj * 8 + (lane >> 2);
    int ci  = ((kt & 3) << 5) + kit;
    int tap = kt >> 2;
    g_wbh[t] = __float2half_rn(w[(((size_t)co * CIN + ci) * NSEL + s) * 9 + tap]);
}

// ---------------------------------------------------------------------------
// Kernel 5: grouped implicit-GEMM conv, fp16 m16n8k16, 64-px tiles.
//   CTA = 64 px x 128 co; 8 warps = 2(M: 32px) x 4(N: 32co); acc 32 regs
//   -> 3 CTAs/SM. A per-pixel work NOT duplicated (unlike N-split); B fills
//   double (cheap, L2-resident). Work grain halves -> smaller tail.
// ---------------------------------------------------------------------------
__global__ void __launch_bounds__(256, 3)
conv_kernel(const float* __restrict__ bias, float* __restrict__ out) {
    const unsigned int bid = blockIdx.x;
    if (bid >= g_tile[NSEL]) return;
    int s = 0;
#pragma unroll
    for (int i = 1; i < NSEL; i++) s += (bid >= g_tile[i]) ? 1 : 0;
    const unsigned int cnt = g_count[s];
    const int tile0 = (int)(bid - g_tile[s]) * PX_TILE;

    extern __shared__ char dsm[];
    const uint32_t Abase = smem_u32(dsm);         // stage layout: [A 8KB | B 16KB] x 3
    unsigned int* spix = (unsigned int*)(dsm + NSTAGE * STAGE_B);

    const int tid  = threadIdx.x;
    const int wid  = tid >> 5;
    const int lane = tid & 31;

    if (tid < PX_TILE) {
        int idx = tile0 + tid;
        spix[tid] = (idx < (int)cnt) ? g_list[s][idx] : INVALID_PIX;
    }
    __syncthreads();

    // ---- gather assignment: px = tid>>2, 32B quarter kg = tid&3 ----
    const int gpx = tid >> 2;                     // 0..63
    const int kg  = tid & 3;
    const unsigned int gp = spix[gpx];
    const bool gvalid = (gp != INVALID_PIX);
    const int gh = (gp >> 7) & 127, gw = gp & 127;
    const size_t pxbase = (size_t)(gp >> 14) << 14;
    // 64B sub-half this quarter belongs to, parity-swizzled; 32B within
    const uint32_t adst_off = (uint32_t)(gpx * 128 +
                              (((kg >> 1) ^ (gpx & 1)) * 64) + (kg & 1) * 32);

    // ---- compute assignment: 8 warps = 2(M: 32px) x 4(N: 32co) ----
    const int wm = wid & 1;
    const int wn = wid >> 1;
    const int rr = lane >> 2;
    const uint32_t kq16 = (uint32_t)(lane & 3) * 16u;

    float acc[2][4][4];
#pragma unroll
    for (int i = 0; i < 2; i++)
#pragma unroll
        for (int j = 0; j < 4; j++)
#pragma unroll
            for (int e = 0; e < 4; e++) acc[i][j][e] = 0.f;

    const char* wtiles = (const char*)g_wbh + (size_t)s * NSUB * 8192;

    // ---- A fill: tap = kt>>1, thread loads 32B contiguous ----
    auto fillA = [&](int kt, int buf) {
        const int tap = kt >> 1;
        const int kh = (tap * 11) >> 5;
        const int kw = tap - kh * 3;
        const int y = gh + kh - 1, x = gw + kw - 1;
        const unsigned int sz =
            (gvalid && (unsigned)y < 128u && (unsigned)x < 128u) ? 16u : 0u;
        const char* src = sz
            ? (const char*)g_in_t + ((pxbase + (size_t)(y * 128 + x)) << 8)
                  + ((kt & 1) << 7) + (kg << 5)
            : (const char*)g_in_t;
        const uint32_t dst = Abase + buf * STAGE_B + adst_off;
        CP_ASYNC16Z(dst,       src,      sz);
        CP_ASYNC16Z(dst + 16u, src + 16, sz);
    };

    // ---- B fill: 16KB tile (2 sub-tiles), 4 cp.async per thread ----
    auto fillB = [&](int kt, int buf) {
        const char* src = wtiles + (size_t)kt * 16384 + tid * 16;
        const uint32_t dst = Abase + buf * STAGE_B + AFRAG_B + (uint32_t)tid * 16u;
        CP_ASYNC16(dst,          src);
        CP_ASYNC16(dst + 4096u,  src + 4096);
        CP_ASYNC16(dst + 8192u,  src + 8192);
        CP_ASYNC16(dst + 12288u, src + 12288);
    };

    auto compute = [&](int buf) {
        const uint32_t Ab = Abase + buf * STAGE_B;
        const uint32_t Bb = Ab + AFRAG_B;
#pragma unroll
        for (int sub = 0; sub < 2; sub++) {
            uint32_t alo[2][4], ahi[2][4];
#pragma unroll
            for (int i = 0; i < 2; i++) {
                const int row = wm * 32 + i * 16 + rr;
                const uint32_t rowa = Ab + (uint32_t)(row * 128) + kq16 +
                                      (uint32_t)(((sub ^ (rr & 1)) * 64));
                LDS128(alo[i], rowa);
                LDS128(ahi[i], rowa + 1024u);        // +8 pixel rows (parity same)
            }
#pragma unroll
            for (int j = 0; j < 4; j++) {
                uint32_t bf[4];
                LDS128(bf, Bb + (uint32_t)(sub * 8192) +
                           (uint32_t)((wn * 4 + j) * 512) + (uint32_t)lane * 16u);
#pragma unroll
                for (int i = 0; i < 2; i++) {
                    mma_f16(acc[i][j], alo[i][0], ahi[i][0], alo[i][1], ahi[i][1],
                            bf[0], bf[1]);           // ci sub*32 + 0..15
                    mma_f16(acc[i][j], alo[i][2], ahi[i][2], alo[i][3], ahi[i][3],
                            bf[2], bf[3]);           // ci sub*32 + 16..31
                }
            }
        }
    };

    // ---------- prologue: stages 0, 1 ----------
    fillB(0, 0); fillA(0, 0); CP_COMMIT();
    fillB(1, 1); fillA(1, 1); CP_COMMIT();
    CP_WAIT1();
    __syncthreads();

    // ---------- main loop ----------
#pragma unroll 1
    for (int kt = 0; kt < NKT; kt++) {
        const int buf = kt % 3;
        const int nb  = (kt + 2) % 3;
        const bool more2 = (kt + 2 < NKT);
        if (more2) { fillB(kt + 2, nb); fillA(kt + 2, nb); CP_COMMIT(); }
        compute(buf);
        if (kt + 1 < NKT) {
            if (more2) { CP_WAIT1(); } else { CP_WAIT0(); }
            __syncthreads();
        }
    }

    // ---------- epilogue: bias + scattered stores ----------
    const int kq = lane & 3;
    float bv[4][2];
#pragma unroll
    for (int j = 0; j < 4; j++) {
        int co = wn * 32 + j * 8 + 2 * kq;
        bv[j][0] = __ldg(&bias[co]);
        bv[j][1] = __ldg(&bias[co + 1]);
    }
#pragma unroll
    for (int i = 0; i < 2; i++) {
        const int r0 = wm * 32 + i * 16 + rr;
#pragma unroll
        for (int half = 0; half < 2; half++) {
            const unsigned int p = spix[r0 + half * 8];
            if (p == INVALID_PIX) continue;
            const int pb = p >> 14;
            const int hw = p & (HWP - 1);
            float* ob = out + ((size_t)pb * COUTC) * HWP + hw;
#pragma unroll
            for (int j = 0; j < 4; j++) {
                const int co = wn * 32 + j * 8 + 2 * kq;
                ob[(size_t)co * HWP]       = acc[i][j][half * 2]     + bv[j][0];
                ob[(size_t)(co + 1) * HWP] = acc[i][j][half * 2 + 1] + bv[j][1];
            }
        }
    }
}

// ---------------------------------------------------------------------------
extern "C" void kernel_launch(void* const* d_in, const int* in_sizes, int n_in,
                              void* d_out, int out_size) {
    const float* input    = (const float*)d_in[0];   // [8,128,128,128]
    const float* selector = (const float*)d_in[1];   // [8,8,128,128]
    const float* weight   = (const float*)d_in[2];   // [128,128,8,3,3]
    const float* bias     = (const float*)d_in[3];   // [128]
    float* out = (float*)d_out;                      // [8,128,128,128]

    static bool attr_done = false;
    if (!attr_done) {
        cudaFuncSetAttribute(conv_kernel, cudaFuncAttributeMaxDynamicSharedMemorySize, SMEM_BYTES);
        attr_done = true;
    }

    tr_kernel<<<dim3(NPIX / 32, CIN / 32), 256>>>(input);
    hist_kernel<<<NBLK, 256>>>(selector);
    scan_kernel<<<1, 256>>>();
    scatter_kernel<<<NBLK, 256>>>();
    reorg_kernel<<<(NSEL * NSUB * 4096) / 256, 256>>>(weight);
    conv_kernel<<<MAXTILES, 256, SMEM_BYTES>>>(bias, out);
}

// round 17
// speedup vs baseline: 1.0978x; 1.0499x over previous
#include <cuda_runtime.h>
#include <cuda_fp16.h>
#include <cstdint>

// ---------------- problem constants ----------------
#define NSEL   8
#define CIN    128
#define COUTC  128
#define HDIM   128
#define WDIM   128
#define HWP    16384            // HDIM*WDIM
#define NPIX   131072           // 8*HWP
#define NELEM  (NPIX * CIN)
#define KC     64               // K per ktile: one tap x 64 ci
#define NKT    18
#define NSUB   36               // reorg sub-tiles (one tap x 32 ci)
#define PX_TILE 128
#define NBLK   512              // NPIX/256
#define MAXTILES 1031
#define INVALID_PIX 0xFFFFFFFFu

// fused prepass block ranges
#define TRBLK   16384           // (NPIX/32) * (CIN/32)
#define PRE_HIST0 TRBLK
#define PRE_REORG0 (TRBLK + NBLK)
#define PREBLK  (TRBLK + NBLK + 4608)

#define AFRAG_B 16384           // 128 px x 128B
#define BFRAG_B 16384           // 2 sub x 16 jj x 32 lanes x 16B
#define NSTAGE  3
#define SMEM_BYTES (NSTAGE*(AFRAG_B+BFRAG_B) + 512)

// ---------------- scratch (static device; no allocs) ----------------
__device__ unsigned int  g_count[NSEL];
__device__ unsigned int  g_tile[NSEL + 1];
__device__ unsigned int  g_list[NSEL][NPIX];                 // 4 MB
__device__ unsigned char g_bs[NPIX];
__device__ unsigned int  g_bhist[NBLK][NSEL];
__device__ unsigned int  g_bbase[NBLK][NSEL];
__device__ __align__(16) __half g_wbh[NSEL * NSUB * 4096];   // 2.25 MB frag-record fp16 B tiles
__device__ __align__(16) __half g_in_t[NELEM];               // 32 MB channel-last fp16 input

// ---------------- PTX helpers ----------------
static __device__ __forceinline__ uint32_t smem_u32(const void* p) {
    uint32_t a;
    asm("{ .reg .u64 t; cvta.to.shared.u64 t, %1; cvt.u32.u64 %0, t; }" : "=r"(a) : "l"(p));
    return a;
}
#define CP_ASYNC16(dst, src) \
    asm volatile("cp.async.cg.shared.global [%0], [%1], 16;" :: "r"(dst), "l"(src))
#define CP_ASYNC16Z(dst, src, sz) \
    asm volatile("cp.async.cg.shared.global [%0], [%1], 16, %2;" :: "r"(dst), "l"(src), "r"(sz))
#define CP_COMMIT() asm volatile("cp.async.commit_group;" ::: "memory")
#define CP_WAIT0()  asm volatile("cp.async.wait_group 0;" ::: "memory")
#define CP_WAIT1()  asm volatile("cp.async.wait_group 1;" ::: "memory")

#define LDS128(v, addr) \
    asm volatile("ld.shared.v4.b32 {%0,%1,%2,%3}, [%4];" \
        : "=r"((v)[0]), "=r"((v)[1]), "=r"((v)[2]), "=r"((v)[3]) : "r"(addr))

static __device__ __forceinline__ void mma_f16(float c[4], uint32_t a0, uint32_t a1,
                                               uint32_t a2, uint32_t a3,
                                               uint32_t b0, uint32_t b1) {
    asm volatile(
        "mma.sync.aligned.m16n8k16.row.col.f32.f16.f16.f32 "
        "{%0,%1,%2,%3}, {%4,%5,%6,%7}, {%8,%9}, {%0,%1,%2,%3};"
        : "+f"(c[0]), "+f"(c[1]), "+f"(c[2]), "+f"(c[3])
        : "r"(a0), "r"(a1), "r"(a2), "r"(a3), "r"(b0), "r"(b1));
}

// pair permutation within each 32-ci block: content pair c at pos = (c&3)*4 + (c>>2)

// ---------------------------------------------------------------------------
// Kernel A (fused prepass): tr + hist + reorg, partitioned by block range.
//   bid <  TRBLK           : input transpose -> g_in_t (channel-last fp16)
//   bid <  TRBLK+NBLK      : argmax gate + per-block histogram
//   else                   : weight repack -> g_wbh
// ---------------------------------------------------------------------------
__global__ void pre_kernel(const float* __restrict__ in,
                           const float* __restrict__ selector,
                           const float* __restrict__ w) {
    __shared__ __align__(16) char shm[32 * 33 * 2];   // tr tile / hist counters
    const unsigned int bid = blockIdx.x;
    const int t = threadIdx.x;

    if (bid < TRBLK) {
        // ---- transpose part ----
        __half (*tile)[33] = (__half(*)[33])shm;
        const int pb = bid >> 2;
        const int cb = bid & 3;

        const int ci_l = t >> 3;
        const int x4   = (t & 7) * 4;
        const int p0   = pb * 32;
        const int b    = p0 >> 14;
        const int hw   = (p0 & (HWP - 1)) + x4;
        float4 v = *(const float4*)(in + ((size_t)b * CIN + cb * 32 + ci_l) * HWP + hw);
        tile[ci_l][x4 + 0] = __float2half_rn(v.x);
        tile[ci_l][x4 + 1] = __float2half_rn(v.y);
        tile[ci_l][x4 + 2] = __float2half_rn(v.z);
        tile[ci_l][x4 + 3] = __float2half_rn(v.w);
        __syncthreads();

        if (t < 128) {
            const int px_l = t >> 2;
            const int u    = t & 3;
            __half h[8];
#pragma unroll
            for (int m = 0; m < 8; m++) {
                int oh  = u * 8 + m;
                int pos = oh >> 1, hi = oh & 1;
                int c   = (pos >> 2) + (pos & 3) * 4;
                h[m] = tile[c * 2 + hi][px_l];
            }
            *(uint4*)((char*)g_in_t + ((size_t)(p0 + px_l) << 8) + (cb << 6) + (u << 4)) =
                *(const uint4*)h;
        }
    } else if (bid < PRE_REORG0) {
        // ---- hist part ----
        unsigned int* h = (unsigned int*)shm;
        const int hb = (int)(bid - PRE_HIST0);
        if (t < NSEL) h[t] = 0u;
        __syncthreads();

        int p  = hb * 256 + t;
        int b  = p >> 14;
        int hw = p & (HWP - 1);
        const float* sp = selector + (size_t)b * NSEL * HWP + hw;
        float best = sp[0];
        int bs = 0;
#pragma unroll
        for (int s = 1; s < NSEL; s++) {
            float v = sp[(size_t)s * HWP];
            if (v > best) { best = v; bs = s; }
        }
        g_bs[p] = (unsigned char)bs;
        atomicAdd(&h[bs], 1u);
        __syncthreads();
        if (t < NSEL) g_bhist[hb][t] = h[t];
    } else {
        // ---- reorg part ----
        int tt0 = (int)(bid - PRE_REORG0) * 256 + t;   // 0 .. NSEL*NSUB*4096-1
        int e    = tt0 & 4095;
        int tile = tt0 >> 12;
        int kt = tile % NSUB;
        int s  = tile / NSUB;
        int m    = e & 7;
        int lane = (e >> 3) & 31;
        int jj   = e >> 8;
        int u4 = m >> 1, hi = m & 1;
        int kq = lane & 3;
        int kit = (kq + u4 * 4) * 2 + hi;
        int co  = jj * 8 + (lane >> 2);
        int ci  = ((kt & 3) << 5) + kit;
        int tap = kt >> 2;
        g_wbh[tt0] = __float2half_rn(w[(((size_t)co * CIN + ci) * NSEL + s) * 9 + tap]);
    }
}

// ---------------------------------------------------------------------------
// Kernel 2: exclusive scan + tile prefix (128-px tiles)
// ---------------------------------------------------------------------------
__global__ void scan_kernel() {
    __shared__ unsigned int part[NSEL][32];
    int tid = threadIdx.x;
    int s = tid & 7, c = tid >> 3;
    unsigned int sum = 0;
#pragma unroll
    for (int b = c * 16; b < c * 16 + 16; b++) sum += g_bhist[b][s];
    part[s][c] = sum;
    __syncthreads();
    if (tid < NSEL) {
        unsigned int run = 0;
#pragma unroll
        for (int c2 = 0; c2 < 32; c2++) {
            unsigned int t = part[tid][c2];
            part[tid][c2] = run;
            run += t;
        }
        g_count[tid] = run;
    }
    __syncthreads();
    unsigned int run = part[s][c];
    for (int b = c * 16; b < c * 16 + 16; b++) {
        g_bbase[b][s] = run;
        run += g_bhist[b][s];
    }
    __syncthreads();
    if (tid == 0) {
        unsigned int tot = 0;
#pragma unroll
        for (int i = 0; i < NSEL; i++) {
            g_tile[i] = tot;
            tot += (g_count[i] + PX_TILE - 1) >> 7;
        }
        g_tile[NSEL] = tot;
    }
}

// ---------------------------------------------------------------------------
// Kernel 3: ordered scatter -> sorted per-bin pixel lists
// ---------------------------------------------------------------------------
__global__ void scatter_kernel() {
    __shared__ unsigned int wh[8][NSEL];
    int tid = threadIdx.x;
    int wid = tid >> 5;
    if (tid < 64) ((unsigned int*)wh)[tid] = 0u;
    __syncthreads();

    int p = blockIdx.x * 256 + tid;
    int bs = g_bs[p];
    unsigned int mask = __match_any_sync(0xFFFFFFFFu, bs);
    unsigned int lt   = (1u << (tid & 31)) - 1u;
    unsigned int rank = __popc(mask & lt);
    if (rank == 0) wh[wid][bs] = __popc(mask);
    __syncthreads();
    if (tid < NSEL) {
        unsigned int run = 0;
#pragma unroll
        for (int w = 0; w < 8; w++) {
            unsigned int t = wh[w][tid];
            wh[w][tid] = run;
            run += t;
        }
    }
    __syncthreads();
    unsigned int idx = g_bbase[blockIdx.x][bs] + wh[wid][bs] + rank;
    g_list[bs][idx] = (unsigned int)p;
}

// ---------------------------------------------------------------------------
// Kernel 4: grouped implicit-GEMM conv, fp16 m16n8k16, KC=64 (R13 verbatim).
// ---------------------------------------------------------------------------
__global__ void __launch_bounds__(256, 2)
conv_kernel(const float* __restrict__ bias, float* __restrict__ out) {
    const unsigned int bid = blockIdx.x;
    if (bid >= g_tile[NSEL]) return;
    int s = 0;
#pragma unroll
    for (int i = 1; i < NSEL; i++) s += (bid >= g_tile[i]) ? 1 : 0;
    const unsigned int cnt = g_count[s];
    const int tile0 = (int)(bid - g_tile[s]) * PX_TILE;

    extern __shared__ char dsm[];
    const uint32_t Abase = smem_u32(dsm);
    const uint32_t Bbase = Abase + NSTAGE * AFRAG_B;
    unsigned int* spix = (unsigned int*)(dsm + NSTAGE * (AFRAG_B + BFRAG_B));

    const int tid  = threadIdx.x;
    const int wid  = tid >> 5;
    const int lane = tid & 31;

    if (tid < PX_TILE) {
        int idx = tile0 + tid;
        spix[tid] = (idx < (int)cnt) ? g_list[s][idx] : INVALID_PIX;
    }
    __syncthreads();

    // ---- gather assignment: px = tid>>1, 64B sub-block kg = tid&1 ----
    const int gpx = tid >> 1;
    const int kg  = tid & 1;
    const unsigned int gp = spix[gpx];
    const bool gvalid = (gp != INVALID_PIX);
    const int gh = (gp >> 7) & 127, gw = gp & 127;
    const size_t pxbase = (size_t)(gp >> 14) << 14;
    const uint32_t asub = (uint32_t)((kg ^ (gpx & 1)) * 64);

    // ---- compute assignment: 8 warps = 2(M) x 4(N) ----
    const int wm = wid & 1;
    const int wn = wid >> 1;
    const int rr = lane >> 2;
    const uint32_t kq16 = (uint32_t)(lane & 3) * 16u;

    float acc[4][4][4];
#pragma unroll
    for (int i = 0; i < 4; i++)
#pragma unroll
        for (int j = 0; j < 4; j++)
#pragma unroll
            for (int e = 0; e < 4; e++) acc[i][j][e] = 0.f;

    const char* wtiles = (const char*)g_wbh + (size_t)s * NKT * 16384;

    auto fillA = [&](int kt, int buf) {
        const int tap = kt >> 1;
        const int kh = (tap * 11) >> 5;
        const int kw = tap - kh * 3;
        const int y = gh + kh - 1, x = gw + kw - 1;
        const unsigned int sz =
            (gvalid && (unsigned)y < 128u && (unsigned)x < 128u) ? 16u : 0u;
        const char* src = sz
            ? (const char*)g_in_t + ((pxbase + (size_t)(y * 128 + x)) << 8)
                  + ((kt & 1) << 7) + (kg << 6)
            : (const char*)g_in_t;
        const uint32_t dst = Abase + buf * AFRAG_B + (uint32_t)gpx * 128u + asub;
        CP_ASYNC16Z(dst,       src,      sz);
        CP_ASYNC16Z(dst + 16u, src + 16, sz);
        CP_ASYNC16Z(dst + 32u, src + 32, sz);
        CP_ASYNC16Z(dst + 48u, src + 48, sz);
    };

    auto fillB = [&](int kt, int buf) {
        const char* src = wtiles + (size_t)kt * 16384 + tid * 16;
        const uint32_t dst = Bbase + buf * BFRAG_B + (uint32_t)tid * 16u;
        CP_ASYNC16(dst,          src);
        CP_ASYNC16(dst + 4096u,  src + 4096);
        CP_ASYNC16(dst + 8192u,  src + 8192);
        CP_ASYNC16(dst + 12288u, src + 12288);
    };

    auto compute = [&](int buf) {
        const uint32_t Ab = Abase + buf * AFRAG_B;
        const uint32_t Bb = Bbase + buf * BFRAG_B;
#pragma unroll
        for (int sub = 0; sub < 2; sub++) {
            uint32_t alo[4][4], ahi[4][4];
#pragma unroll
            for (int i = 0; i < 4; i++) {
                const int row = wm * 64 + i * 16 + rr;
                const uint32_t rowa = Ab + (uint32_t)(row * 128) + kq16 +
                                      (uint32_t)(((sub ^ (rr & 1)) * 64));
                LDS128(alo[i], rowa);
                LDS128(ahi[i], rowa + 1024u);
            }
#pragma unroll
            for (int j = 0; j < 4; j++) {
                uint32_t bf[4];
                LDS128(bf, Bb + (uint32_t)(sub * 8192) +
                           (uint32_t)((wn * 4 + j) * 512) + (uint32_t)lane * 16u);
#pragma unroll
                for (int i = 0; i < 4; i++) {
                    mma_f16(acc[i][j], alo[i][0], ahi[i][0], alo[i][1], ahi[i][1],
                            bf[0], bf[1]);
                    mma_f16(acc[i][j], alo[i][2], ahi[i][2], alo[i][3], ahi[i][3],
                            bf[2], bf[3]);
                }
            }
        }
    };

    // ---------- prologue: stages 0, 1 ----------
    fillB(0, 0); fillA(0, 0); CP_COMMIT();
    fillB(1, 1); fillA(1, 1); CP_COMMIT();
    CP_WAIT1();
    __syncthreads();

    // ---------- main loop ----------
#pragma unroll 1
    for (int kt = 0; kt < NKT; kt++) {
        const int buf = kt % 3;
        const int nb  = (kt + 2) % 3;
        const bool more2 = (kt + 2 < NKT);
        if (more2) { fillB(kt + 2, nb); fillA(kt + 2, nb); CP_COMMIT(); }
        compute(buf);
        if (kt + 1 < NKT) {
            if (more2) { CP_WAIT1(); } else { CP_WAIT0(); }
            __syncthreads();
        }
    }

    // ---------- epilogue: bias + scattered stores ----------
    const int kq = lane & 3;
    float bv[4][2];
#pragma unroll
    for (int j = 0; j < 4; j++) {
        int co = wn * 32 + j * 8 + 2 * kq;
        bv[j][0] = __ldg(&bias[co]);
        bv[j][1] = __ldg(&bias[co + 1]);
    }
#pragma unroll
    for (int i = 0; i < 4; i++) {
        const int r0 = wm * 64 + i * 16 + rr;
#pragma unroll
        for (int half = 0; half < 2; half++) {
            const unsigned int p = spix[r0 + half * 8];
            if (p == INVALID_PIX) continue;
            const int pb = p >> 14;
            const int hw = p & (HWP - 1);
            float* ob = out + ((size_t)pb * COUTC) * HWP + hw;
#pragma unroll
            for (int j = 0; j < 4; j++) {
                const int co = wn * 32 + j * 8 + 2 * kq;
                ob[(size_t)co * HWP]       = acc[i][j][half * 2]     + bv[j][0];
                ob[(size_t)(co + 1) * HWP] = acc[i][j][half * 2 + 1] + bv[j][1];
            }
        }
    }
}

// ---------------------------------------------------------------------------
extern "C" void kernel_launch(void* const* d_in, const int* in_sizes, int n_in,
                              void* d_out, int out_size) {
    const float* input    = (const float*)d_in[0];   // [8,128,128,128]
    const float* selector = (const float*)d_in[1];   // [8,8,128,128]
    const float* weight   = (const float*)d_in[2];   // [128,128,8,3,3]
    const float* bias     = (const float*)d_in[3];   // [128]
    float* out = (float*)d_out;                      // [8,128,128,128]

    static bool attr_done = false;
    if (!attr_done) {
        cudaFuncSetAttribute(conv_kernel, cudaFuncAttributeMaxDynamicSharedMemorySize, SMEM_BYTES);
        attr_done = true;
    }

    pre_kernel<<<PREBLK, 256>>>(input, selector, weight);
    scan_kernel<<<1, 256>>>();
    scatter_kernel<<<NBLK, 256>>>();
    conv_kernel<<<MAXTILES, 256, SMEM_BYTES>>>(bias, out);
}